// round 9
// baseline (speedup 1.0000x reference)
#include <cuda_runtime.h>
#include <stdint.h>

#define NN 262144
#define NE (4*1024*1024)

typedef unsigned long long ull;

// Scratch (device globals — no allocation allowed)
__device__ float g_h0[NN * 16];                 // layer-0 input, padded 9->16 (stride 16)
__device__ float g_hl[4][NN * 32];              // DENSE per-layer outputs (32MB each, L2-resident)
__device__ float g_agg[NN * 32];                // gather output (fully overwritten each layer)
__device__ float g_zpre[NN * 32];               // pre-BN MLP output
__device__ float g_stats[256];                  // per layer: [l*64+c]=sum, [l*64+32+c]=sumsq
__device__ float g_part[1024][64];              // stats partials (no global atomics)
// CSR-by-dst scratch
__device__ int g_deg[NN];
__device__ int g_off[NN + 1];
__device__ int g_pos[NN];
__device__ int g_csr[NE];
__device__ int g_bsum[256];
__device__ int g_bsum2[256];

// packed f32x2 helpers (FFMA2 is PTX-only on sm_103a)
__device__ __forceinline__ ull pk2(float a, float b) {
    ull r; asm("mov.b64 %0,{%1,%2};" : "=l"(r) : "f"(a), "f"(b)); return r;
}
__device__ __forceinline__ void upk2(ull v, float& a, float& b) {
    asm("mov.b64 {%0,%1},%2;" : "=f"(a), "=f"(b) : "l"(v));
}
__device__ __forceinline__ ull fma2(ull a, ull b, ull c) {
    ull d; asm("fma.rn.f32x2 %0,%1,%2,%3;" : "=l"(d) : "l"(a), "l"(b), "l"(c)); return d;
}

// ---------------------------------------------------------------------------
// init: zero deg + stats, build h0 = cat(x, t, 0-pad) with stride 16
// ---------------------------------------------------------------------------
__global__ void k_init(const float* __restrict__ x, const float* __restrict__ t) {
    int i = blockIdx.x * blockDim.x + threadIdx.x;
    if (i < NN * 16) {
        int n = i >> 4, k = i & 15;
        float v = 0.f;
        if (k < 8) v = x[n * 8 + k];
        else if (k == 8) v = t[0];
        g_h0[i] = v;
    }
    if (i < NN) g_deg[i] = 0;
}

// ---------------------------------------------------------------------------
// CSR build: count, scan (2-level), fill
// ---------------------------------------------------------------------------
__global__ void k_count(const int* __restrict__ dst) {
    int e = blockIdx.x * blockDim.x + threadIdx.x;
    if (e < NE) atomicAdd(&g_deg[dst[e]], 1);
}

__global__ void k_scan1() {   // 256 blocks x 1024 threads: per-block exclusive scan
    __shared__ int s[1024];
    int tid = threadIdx.x;
    int i = blockIdx.x * 1024 + tid;
    int v = g_deg[i];
    s[tid] = v;
    __syncthreads();
#pragma unroll
    for (int off = 1; off < 1024; off <<= 1) {
        int tv = (tid >= off) ? s[tid - off] : 0;
        __syncthreads();
        s[tid] += tv;
        __syncthreads();
    }
    g_off[i] = s[tid] - v;                 // exclusive
    if (tid == 1023) g_bsum[blockIdx.x] = s[1023];
}

__global__ void k_scan2() {   // 1 block x 256 threads: exclusive scan of block sums
    __shared__ int s[256];
    int tid = threadIdx.x;
    int v = g_bsum[tid];
    s[tid] = v;
    __syncthreads();
#pragma unroll
    for (int off = 1; off < 256; off <<= 1) {
        int tv = (tid >= off) ? s[tid - off] : 0;
        __syncthreads();
        s[tid] += tv;
        __syncthreads();
    }
    g_bsum2[tid] = s[tid] - v;
}

__global__ void k_scan3() {
    int i = blockIdx.x * blockDim.x + threadIdx.x;
    if (i < NN) {
        int o = g_off[i] + g_bsum2[i >> 10];
        g_off[i] = o;
        g_pos[i] = o;
    }
    if (i == 0) g_off[NN] = NE;
}

__global__ void k_fill(const int* __restrict__ src, const int* __restrict__ dst) {
    int e = blockIdx.x * blockDim.x + threadIdx.x;
    if (e >= NE) return;
    int slot = atomicAdd(&g_pos[dst[e]], 1);
    g_csr[slot] = src[e];
}

// ---------------------------------------------------------------------------
// gather: chunk-per-thread (sector-perfect: adjacent lanes of a node cover a
// full source row in lockstep). SHIFT=log2(chunks), ST=src row stride floats.
// ---------------------------------------------------------------------------
template<int SHIFT, int ST>
__global__ void __launch_bounds__(256) k_gather(const float* __restrict__ hbase) {
    int idx = blockIdx.x * blockDim.x + threadIdx.x;
    int n = idx >> SHIFT;
    int c = idx & ((1 << SHIFT) - 1);
    if (n >= NN) return;
    int k = g_off[n], end = g_off[n + 1];
    float ax = 0.f, ay = 0.f, az = 0.f, aw = 0.f;
    for (; k + 4 <= end; k += 4) {
        int s0 = g_csr[k], s1 = g_csr[k + 1], s2 = g_csr[k + 2], s3 = g_csr[k + 3];
        float4 v0 = *(const float4*)(hbase + (size_t)s0 * ST + c * 4);
        float4 v1 = *(const float4*)(hbase + (size_t)s1 * ST + c * 4);
        float4 v2 = *(const float4*)(hbase + (size_t)s2 * ST + c * 4);
        float4 v3 = *(const float4*)(hbase + (size_t)s3 * ST + c * 4);
        ax += (v0.x + v1.x) + (v2.x + v3.x);
        ay += (v0.y + v1.y) + (v2.y + v3.y);
        az += (v0.z + v1.z) + (v2.z + v3.z);
        aw += (v0.w + v1.w) + (v2.w + v3.w);
    }
    for (; k < end; k++) {
        int s0 = g_csr[k];
        float4 v0 = *(const float4*)(hbase + (size_t)s0 * ST + c * 4);
        ax += v0.x; ay += v0.y; az += v0.z; aw += v0.w;
    }
    float4 o; o.x = ax; o.y = ay; o.z = az; o.w = aw;
    *(float4*)(g_agg + (size_t)n * 32 + c * 4) = o;
}

// ---------------------------------------------------------------------------
// node MLP (packed f32x2): z=(1+eps)h+agg; u=relu(z@W1+b1); v=u@W2+b2 -> g_zpre
// ---------------------------------------------------------------------------
template<int K, int KROWS, int HST>
__global__ void __launch_bounds__(128) k_node(
    const float* __restrict__ hprev,
    const float* __restrict__ W1, const float* __restrict__ b1,
    const float* __restrict__ W2, const float* __restrict__ b2,
    const float* __restrict__ eps, int l)
{
    __shared__ __align__(16) float sW1[K * 32];
    __shared__ __align__(16) float sW2[32 * 32];
    __shared__ __align__(16) float sb1[32];
    __shared__ __align__(16) float sb2[32];
    int tid = threadIdx.x;
    for (int i = tid; i < K * 32; i += 128) {
        int k = i >> 5;
        sW1[i] = (k < KROWS) ? W1[i] : 0.f;
    }
    for (int i = tid; i < 1024; i += 128) sW2[i] = W2[i];
    if (tid < 32) { sb1[tid] = b1[tid]; sb2[tid] = b2[tid]; }
    __syncthreads();

    int n = blockIdx.x * 128 + tid;
    if (n >= NN) return;
    float e1 = 1.f + eps[l];
    const float* hp = hprev + (size_t)n * HST;
    const float* ap = g_agg + (size_t)n * 32;

    float z[K];
#pragma unroll
    for (int k = 0; k < K; k += 4) {
        float4 h4 = *(const float4*)(hp + k);
        float4 a4 = *(const float4*)(ap + k);
        z[k + 0] = fmaf(e1, h4.x, a4.x);
        z[k + 1] = fmaf(e1, h4.y, a4.y);
        z[k + 2] = fmaf(e1, h4.z, a4.z);
        z[k + 3] = fmaf(e1, h4.w, a4.w);
    }

    // GEMM1: u2[16] packed pairs of output channels
    ull u2[16];
    const ull* b1p = (const ull*)sb1;
#pragma unroll
    for (int jj = 0; jj < 16; jj++) u2[jj] = b1p[jj];
#pragma unroll
    for (int k = 0; k < K; k++) {
        ull zz = pk2(z[k], z[k]);
        const ulonglong2* w = (const ulonglong2*)&sW1[k << 5];
#pragma unroll
        for (int jj = 0; jj < 8; jj++) {
            ulonglong2 wv = w[jj];
            u2[2 * jj + 0] = fma2(zz, wv.x, u2[2 * jj + 0]);
            u2[2 * jj + 1] = fma2(zz, wv.y, u2[2 * jj + 1]);
        }
    }
    // ReLU (unpack to scalars; GEMM2 needs scalar broadcast anyway)
    float u[32];
#pragma unroll
    for (int jj = 0; jj < 16; jj++) upk2(u2[jj], u[2 * jj], u[2 * jj + 1]);
#pragma unroll
    for (int j = 0; j < 32; j++) u[j] = fmaxf(u[j], 0.f);

    // GEMM2: v2[16] packed pairs
    ull v2[16];
    const ull* b2p = (const ull*)sb2;
#pragma unroll
    for (int jj = 0; jj < 16; jj++) v2[jj] = b2p[jj];
#pragma unroll
    for (int k = 0; k < 32; k++) {
        ull uu = pk2(u[k], u[k]);
        const ulonglong2* w = (const ulonglong2*)&sW2[k << 5];
#pragma unroll
        for (int jj = 0; jj < 8; jj++) {
            ulonglong2 wv = w[jj];
            v2[2 * jj + 0] = fma2(uu, wv.x, v2[2 * jj + 0]);
            v2[2 * jj + 1] = fma2(uu, wv.y, v2[2 * jj + 1]);
        }
    }

    ulonglong2* zp = (ulonglong2*)(g_zpre + (size_t)n * 32);
#pragma unroll
    for (int q = 0; q < 8; q++) {
        ulonglong2 o; o.x = v2[2 * q]; o.y = v2[2 * q + 1];
        zp[q] = o;
    }
}

// ---------------------------------------------------------------------------
// BN stats stage A: per-block partials -> g_part (plain stores, no g-atomics)
// ---------------------------------------------------------------------------
__global__ void k_statsA() {
    int lane = threadIdx.x & 31;
    int warpId = (blockIdx.x * blockDim.x + threadIdx.x) >> 5;
    int nwarps = (gridDim.x * blockDim.x) >> 5;
    float s = 0.f, q = 0.f;
    for (int n = warpId; n < NN; n += nwarps) {
        float v = g_zpre[(size_t)n * 32 + lane];
        s += v;
        q += v * v;
    }
    __shared__ float ss[32], sq[32];
    if (threadIdx.x < 32) { ss[threadIdx.x] = 0.f; sq[threadIdx.x] = 0.f; }
    __syncthreads();
    atomicAdd(&ss[lane], s);
    atomicAdd(&sq[lane], q);
    __syncthreads();
    if (threadIdx.x < 64) {
        float v = (threadIdx.x < 32) ? ss[threadIdx.x] : sq[threadIdx.x - 32];
        g_part[blockIdx.x][threadIdx.x] = v;
    }
}

// stage B: reduce 1024 x 64 partials -> g_stats[l*64 + c]
__global__ void k_statsB(int l) {
    int tid = threadIdx.x;            // 256 threads
    int c = tid & 63;
    int grp = tid >> 6;               // 0..3
    float s = 0.f;
    for (int i = grp; i < 1024; i += 4) s += g_part[i][c];
    __shared__ float red[4][64];
    red[grp][c] = s;
    __syncthreads();
    if (tid < 64) g_stats[l * 64 + tid] = red[0][tid] + red[1][tid] + red[2][tid] + red[3][tid];
}

// ---------------------------------------------------------------------------
// BN + ReLU -> dense layer output buffer
// ---------------------------------------------------------------------------
__global__ void k_bn(const float* __restrict__ gamma, const float* __restrict__ beta, int l) {
    int i = blockIdx.x * blockDim.x + threadIdx.x;
    if (i >= NN * 32) return;
    int c = i & 31;
    const float inv = 1.0f / (float)NN;
    float mu = g_stats[l * 64 + c] * inv;
    float var = g_stats[l * 64 + 32 + c] * inv - mu * mu;
    float rs = rsqrtf(var + 1e-5f);
    float g = gamma[l * 32 + c], b = beta[l * 32 + c];
    float val = (g_zpre[i] - mu) * rs * g + b;
    g_hl[l][i] = fmaxf(val, 0.f);
}

// ---------------------------------------------------------------------------
// final: new_x = cat(h0..h3) @ lin_W + lin_b; masked write-back (int32 masks)
// ---------------------------------------------------------------------------
__global__ void __launch_bounds__(128) k_final(
    const float* __restrict__ x, const float* __restrict__ linW,
    const float* __restrict__ linb,
    const int* __restrict__ nmask, const int* __restrict__ emask,
    const int* __restrict__ ondp, const int* __restrict__ oedp,
    float* __restrict__ out)
{
    __shared__ __align__(16) float sW[128 * 8];
    __shared__ __align__(16) float sb[8];
    int tid = threadIdx.x;
    for (int i = tid; i < 1024; i += 128) sW[i] = linW[i];
    if (tid < 8) sb[tid] = linb[tid];
    __syncthreads();

    int n = blockIdx.x * 128 + tid;
    if (n >= NN) return;

    ull acc2[4];
    const ull* sbp = (const ull*)sb;
#pragma unroll
    for (int j = 0; j < 4; j++) acc2[j] = sbp[j];
#pragma unroll
    for (int l = 0; l < 4; l++) {
        const float* cp = &g_hl[l][(size_t)n * 32];
#pragma unroll 8
        for (int k = 0; k < 32; k += 4) {
            float4 cv = *(const float4*)(cp + k);
            float ck[4] = {cv.x, cv.y, cv.z, cv.w};
#pragma unroll
            for (int kk = 0; kk < 4; kk++) {
                const ulonglong2* w = (const ulonglong2*)&sW[(l * 32 + k + kk) * 8];
                ulonglong2 w0 = w[0], w1 = w[1];
                ull cc = pk2(ck[kk], ck[kk]);
                acc2[0] = fma2(cc, w0.x, acc2[0]);
                acc2[1] = fma2(cc, w0.y, acc2[1]);
                acc2[2] = fma2(cc, w1.x, acc2[2]);
                acc2[3] = fma2(cc, w1.y, acc2[3]);
            }
        }
    }
    float acc[8];
#pragma unroll
    for (int j = 0; j < 4; j++) upk2(acc2[j], acc[2 * j], acc[2 * j + 1]);

    int ond = ondp[0], oed = oedp[0];
    bool nm = nmask[n] != 0;
    bool em = emask[n] != 0;
#pragma unroll
    for (int j = 0; j < 8; j++) {
        bool take = (j >= 1) && ((nm && j < ond + 1) || (em && j < oed + 1));
        out[(size_t)n * 8 + j] = take ? acc[j] : x[(size_t)n * 8 + j];
    }
}

// ---------------------------------------------------------------------------
extern "C" void kernel_launch(void* const* d_in, const int* in_sizes, int n_in,
                              void* d_out, int out_size) {
    const float* x     = (const float*)d_in[0];
    const float* t     = (const float*)d_in[1];
    const int*   ei    = (const int*)d_in[2];
    const int*   nmask = (const int*)d_in[3];
    const int*   emask = (const int*)d_in[4];
    const int*   ondp  = (const int*)d_in[5];
    const int*   oedp  = (const int*)d_in[6];
    const float* W1f   = (const float*)d_in[7];
    const float* b1f   = (const float*)d_in[8];
    const float* W2f   = (const float*)d_in[9];
    const float* b2f   = (const float*)d_in[10];
    const float* W1r   = (const float*)d_in[11];
    const float* b1r   = (const float*)d_in[12];
    const float* W2r   = (const float*)d_in[13];
    const float* b2r   = (const float*)d_in[14];
    const float* eps   = (const float*)d_in[15];
    const float* gam   = (const float*)d_in[16];
    const float* bet   = (const float*)d_in[17];
    const float* linW  = (const float*)d_in[18];
    const float* linb  = (const float*)d_in[19];
    float* out = (float*)d_out;

    const int* src = ei;
    const int* dst = ei + NE;

    // init + CSR build (once per launch)
    k_init<<<(NN * 16) / 256, 256>>>(x, t);
    k_count<<<NE / 256, 256>>>(dst);
    k_scan1<<<256, 1024>>>();
    k_scan2<<<1, 256>>>();
    k_scan3<<<NN / 256, 256>>>();
    k_fill<<<NE / 256, 256>>>(src, dst);

    float* h0p;  cudaGetSymbolAddress((void**)&h0p, g_h0);
    float* hlp;  cudaGetSymbolAddress((void**)&hlp, g_hl);

    // layer 0 (padded K=12, h0 stride 16; 4 chunk-threads per node)
    k_gather<2, 16><<<(NN * 4) / 256, 256>>>(h0p);
    k_node<12, 9, 16><<<NN / 128, 128>>>(h0p, W1f, b1f, W2f, b2f, eps, 0);
    k_statsA<<<1024, 256>>>();
    k_statsB<<<1, 256>>>(0);
    k_bn<<<(NN * 32) / 256, 256>>>(gam, bet, 0);

    // layers 1..3 (dense 32-float rows; 8 chunk-threads per node)
    for (int l = 1; l < 4; l++) {
        const float* hprev = hlp + (size_t)(l - 1) * NN * 32;
        k_gather<3, 32><<<(NN * 8) / 256, 256>>>(hprev);
        k_node<32, 32, 32><<<NN / 128, 128>>>(hprev,
                                              W1r + (l - 1) * 1024, b1r + (l - 1) * 32,
                                              W2r + (l - 1) * 1024, b2r + (l - 1) * 32,
                                              eps, l);
        k_statsA<<<1024, 256>>>();
        k_statsB<<<1, 256>>>(l);
        k_bn<<<(NN * 32) / 256, 256>>>(gam, bet, l);
    }

    k_final<<<NN / 128, 128>>>(x, linW, linb, nmask, emask, ondp, oedp, out);
}